// round 10
// baseline (speedup 1.0000x reference)
#include <cuda_runtime.h>

constexpr int HH = 512;
constexpr int WW = 512;
constexpr int NB = 9;
constexpr int OH = 32;
constexpr int OW = 32;
constexpr int BMAX = 8;

#define PIF 3.14159265358979323846f

// ---------------- scratch ----------------
__device__ float2 g_vab[BMAX * HH * WW];           // (wa*I, wb*I) per pixel
__device__ unsigned char g_k0[BMAX * HH * WW];     // base bin in [0,7]
__device__ float g_hog [BMAX * NB * OH * OW];
__device__ float g_maxn[BMAX];                     // atomicMax accumulator (>=0)
__device__ float g_tmp [BMAX * 2 * OH * WW];       // horizontally-resized rows
__device__ float g_wt  [WW * 6];
__device__ int   g_ws  [WW];

// ---------------- fused grayscale + gradient + bin decomposition (+ lanczos wt fold) ----------------
__global__ void grad_kernel(const float* __restrict__ x) {
    __shared__ float sg[10][34];
    int b = blockIdx.z;
    int x0 = blockIdx.x * 32, y0 = blockIdx.y * 8;
    const float* xb = x + (size_t)b * 3 * HH * WW;
    int tid = threadIdx.y * 32 + threadIdx.x;

    if (tid == 0) g_maxn[b] = 0.0f;   // reset for hog's atomicMax

    // fold: lanczos3 weight table, computed once by the first row of blocks of batch 0
    if (blockIdx.z == 0 && blockIdx.y == 0) {
        int o = blockIdx.x * 256 + tid;
        if (o < WW) {
            float sf = (o + 0.5f) * 0.0625f - 0.5f;
            int i0 = (int)floorf(sf) - 2;
            float w[6];
            float tot = 0.0f;
#pragma unroll
            for (int j = 0; j < 6; j++) {
                int ii = i0 + j;
                float val = 0.0f;
                if (ii >= 0 && ii < OW) {
                    float xx = fabsf(sf - (float)ii);
                    float px1 = PIF * xx;
                    float s1 = (xx == 0.0f) ? 1.0f : (sinf(px1) / px1);
                    float x3 = xx / 3.0f;
                    float px3 = PIF * x3;
                    float s3 = (x3 == 0.0f) ? 1.0f : (sinf(px3) / px3);
                    val = 3.0f * s1 * s3;
                }
                w[j] = val;
                tot += val;
            }
#pragma unroll
            for (int j = 0; j < 6; j++) g_wt[o * 6 + j] = w[j] / tot;
            g_ws[o] = i0;
        }
    }

    for (int i = tid; i < 10 * 34; i += 256) {
        int ly = i / 34, lx = i - ly * 34;
        int gy = y0 + ly - 1, gx = x0 + lx - 1;
        float v = 0.0f;
        if (gy >= 0 && gy < HH && gx >= 0 && gx < WW) {
            int p = gy * WW + gx;
            v = 0.299f * xb[p] + 0.587f * xb[p + HH * WW] + 0.114f * xb[p + 2 * HH * WW];
        }
        sg[ly][lx] = v;
    }
    __syncthreads();

    int lx = threadIdx.x, ly = threadIdx.y;
    float gx = sg[ly + 1][lx + 2] - sg[ly + 1][lx];
    float gy = sg[ly + 2][lx + 1] - sg[ly][lx + 1];
    float inten = sqrtf(gx * gx + gy * gy);
    float a = atan2f(gy, gx) + PIF;      // >= 0
    float r = fmodf(a, PIF);             // jnp.mod (positive arg) == fmod
    float o = r / PIF * 180.0f;          // [0,180)

    int k0 = (int)floorf((o - 10.0f) * 0.05f);   // [-1,8]
    float c0 = 10.0f + 20.0f * (float)k0;
    float wa = fminf(fmaxf(1.0f - (fabsf(o - c0) * 9.0f) / 180.0f, 0.0f), 1.0f);
    float wb = fminf(fmaxf(1.0f - (fabsf(o - (c0 + 20.0f)) * 9.0f) / 180.0f, 0.0f), 1.0f);
    float va = wa * inten, vb = wb * inten;
    if (k0 < 0)      { k0 = 0; va = vb; vb = 0.0f; }
    else if (k0 > 7) { k0 = 7; vb = va; va = 0.0f; }

    int p = b * HH * WW + (y0 + ly) * WW + (x0 + lx);
    g_vab[p] = make_float2(va, vb);
    g_k0[p] = (unsigned char)k0;
}

__device__ __forceinline__ int refl(int m) {
    m = (m < 0) ? -m : m;
    m = (m > HH - 1) ? (2 * (HH - 1) - m) : m;
    return m;
}

// ---------------- HOG aggregation + fused per-cell norm -> atomicMax ----------------
__global__ void hog_kernel() {
    __shared__ float sacc[NB][256];     // bank(tid) independent of bin -> conflict-free
    __shared__ int srow[33], scol[33];
    __shared__ float sbin[NB];
    int b = blockIdx.y;
    int cell = blockIdx.x;
    int oy = cell >> 5, ox = cell & 31;
    int tid = threadIdx.x;

    if (tid < 33) {
        srow[tid] = refl(oy * 16 - 16 + tid) * WW;
        scol[tid] = refl(ox * 16 - 16 + tid);
    }
#pragma unroll
    for (int k = 0; k < NB; k++) sacc[k][tid] = 0.0f;
    __syncthreads();

    const float2* __restrict__ V = g_vab + b * HH * WW;
    const unsigned char* __restrict__ K = g_k0 + b * HH * WW;

    // 1089 taps: 4 per thread + tail of 65
    float2 v[4]; float f[4]; int kk[4];
#pragma unroll
    for (int j = 0; j < 4; j++) {
        int t = tid + j * 256;
        int dy = t / 33;
        int dx = t - dy * 33;
        int gi = srow[dy] + scol[dx];
        v[j] = __ldg(&V[gi]);
        kk[j] = (int)K[gi];
        float fy = (float)(dy - 16), fx = (float)(dx - 16);
        f[j] = 1.0f - sqrtf(fy * fy + fx * fx) / 22.627417f;
    }
#pragma unroll
    for (int j = 0; j < 4; j++) {
        sacc[kk[j]][tid]     += f[j] * v[j].x;
        sacc[kk[j] + 1][tid] += f[j] * v[j].y;
    }
    if (tid < 65) {
        int t = 1024 + tid;
        int dy = t / 33;
        int dx = t - dy * 33;
        int gi = srow[dy] + scol[dx];
        float2 vt = __ldg(&V[gi]);
        int kt = (int)K[gi];
        float fy = (float)(dy - 16), fx = (float)(dx - 16);
        float ft = 1.0f - sqrtf(fy * fy + fx * fx) / 22.627417f;
        sacc[kt][tid]     += ft * vt.x;
        sacc[kt + 1][tid] += ft * vt.y;
    }
    __syncthreads();

    // warp w reduces bins k = w, w+8 (strided LDS + shuffle tree)
    int w = tid >> 5, l = tid & 31;
    for (int k = w; k < NB; k += 8) {
        float s = 0.0f;
#pragma unroll
        for (int i = 0; i < 8; i++) s += sacc[k][l + 32 * i];
#pragma unroll
        for (int off = 16; off > 0; off >>= 1)
            s += __shfl_down_sync(0xffffffffu, s, off);
        if (l == 0) {
            g_hog[(b * NB + k) * (OH * OW) + cell] = s;
            sbin[k] = s;
        }
    }
    __syncthreads();

    // cell L2 norm over bins -> per-batch max (atomic on int view; all values >= 0)
    if (tid == 0) {
        float s2 = 0.0f;
#pragma unroll
        for (int k = 0; k < NB; k++) s2 += sbin[k] * sbin[k];
        atomicMax((int*)&g_maxn[b], __float_as_int(sqrtf(s2)));
    }
}

// ---------------- fused dominant-direction + quantize + horizontal lanczos pass ----------------
// block = (row, b): dom for 32 cells of this row (threads 0-31), then hpass 2ch x 512.
__global__ void domh_kernel() {
    __shared__ float qs[2][OW];
    int b = blockIdx.y;
    int row = blockIdx.x;              // 0..31
    int tid = threadIdx.x;             // 256

    if (tid < OW) {
        int p = row * OW + tid;
        float maxn = g_maxn[b];
        float A = 0.0f, Cc = 0.0f, Bs = 0.0f;
#pragma unroll
        for (int k = 0; k < NB; k++) {
            float ck = 10.0f + 20.0f * (float)k;
            float th = (ck / 180.0f) * PIF;
            float sn = sinf(th), cs = cosf(th);
            float hn = g_hog[(b * NB + k) * (OH * OW) + p] / maxn;
            float h2 = hn * hn;
            A  += (sn * sn) * h2;
            Cc += (cs * cs) * h2;
            Bs += (sn * cs) * h2;
        }
        float Bb = -Bs;
        float half = (A - Cc) * 0.5f;
        float lam = (A + Cc) * 0.5f + sqrtf(half * half + Bb * Bb);
        float la = lam - A, lc = lam - Cc;
        float n1 = Bb * Bb + la * la;
        float n2 = lc * lc + Bb * Bb;
        bool use1 = (n1 >= n2);
        float vx = use1 ? Bb : lc;
        float vy = use1 ? la : Bb;
        float nrm = sqrtf(vx * vx + vy * vy) + 1e-9f;
        qs[0][tid] = floorf((vx / nrm + 1.0f) / 2.0f * 255.0f);
        qs[1][tid] = floorf((vy / nrm + 1.0f) / 2.0f * 255.0f);
    }
    __syncthreads();

    // horizontal pass: 2 channels x 512 outputs
    for (int i = tid; i < 2 * WW; i += 256) {
        int c = i >> 9;
        int xo = i & 511;
        int st = g_ws[xo];
        float s = 0.0f;
#pragma unroll
        for (int j = 0; j < 6; j++) {
            int idx = min(max(st + j, 0), OW - 1);
            s += g_wt[xo * 6 + j] * qs[c][idx];
        }
        g_tmp[(b * 2 + c) * (OH * WW) + row * WW + xo] = s;
    }
}

// ---------------- vertical pass + epilogue: shared-staged 16-row x 256-col tile ----------------
// block = (yt 0..31, xh 0..1, b): stage 7 tmp rows x 256 cols x 2ch in shared,
// emit 16 output rows x 256 cols x 2ch.
__global__ void vpass_kernel(float* __restrict__ out) {
    __shared__ float stmp[2][7][256];   // 14 KB, x fastest -> conflict-free float4
    int yt = blockIdx.x;
    int xh = blockIdx.y;
    int b = blockIdx.z;
    int tid = threadIdx.x;              // 256
    int xbase = xh * 256;
    int rbase = yt - 3;                 // tap rows rbase..rbase+6 (pre-clamp)

    // stage: 2ch x 7 rows x 64 quads = 896 float4 loads
    for (int i = tid; i < 896; i += 256) {
        int c = i / 448;
        int rem = i - c * 448;
        int rr = rem >> 6;              // 0..6
        int qx = rem & 63;
        int row = min(max(rbase + rr, 0), OH - 1);
        float4 v = __ldg((const float4*)(g_tmp + (b * 2 + c) * (OH * WW) + row * WW + xbase + qx * 4));
        *(float4*)&stmp[c][rr][qx * 4] = v;
    }
    __syncthreads();

    // emit: 16 rows x 64 quads (each thread 4 quads)
    for (int i = tid; i < 1024; i += 256) {
        int ry = i >> 6;
        int qx = i & 63;
        int y = yt * 16 + ry;
        int st = __ldg(&g_ws[y]);
        int lr0 = st - rbase;           // 0 or 1; lr in [0,6]

        float4 r0 = make_float4(0.f, 0.f, 0.f, 0.f);
        float4 r1 = make_float4(0.f, 0.f, 0.f, 0.f);
#pragma unroll
        for (int j = 0; j < 6; j++) {
            float wj = __ldg(&g_wt[y * 6 + j]);
            float4 a = *(const float4*)&stmp[0][lr0 + j][qx * 4];
            float4 c = *(const float4*)&stmp[1][lr0 + j][qx * 4];
            r0.x += wj * a.x; r0.y += wj * a.y; r0.z += wj * a.z; r0.w += wj * a.w;
            r1.x += wj * c.x; r1.y += wj * c.y; r1.z += wj * c.z; r1.w += wj * c.w;
        }

        float4 o0, o1;
        float* pr0 = &r0.x; float* pr1 = &r1.x;
        float* po0 = &o0.x; float* po1 = &o1.x;
#pragma unroll
        for (int q = 0; q < 4; q++) {
            float a = fminf(fmaxf(rintf(pr0[q]), 0.0f), 255.0f);
            float c = fminf(fmaxf(rintf(pr1[q]), 0.0f), 255.0f);
            float u = fmaf(a, 0.003921568859f, -0.5f) * 2.0f;   // a*(1/255) - 0.5, then *2
            float v = fmaf(c, 0.003921568859f, -0.5f) * 2.0f;
            float inn = __frcp_rn(sqrtf(u * u + v * v));        // 1/||.||, then 2 muls
            po0[q] = u * inn;
            po1[q] = v * inn;
        }
        size_t o = ((size_t)(b * 2 + 0) * HH + y) * WW + xbase + qx * 4;
        *(float4*)(out + o) = o0;
        *(float4*)(out + o + (size_t)2 * HH * WW * 0 + (size_t)HH * WW) = o1;   // channel 1 plane
    }
}

// ---------------- launch ----------------
extern "C" void kernel_launch(void* const* d_in, const int* in_sizes, int n_in,
                              void* d_out, int out_size) {
    const float* x = (const float*)d_in[0];
    int B = in_sizes[0] / (3 * HH * WW);
    if (B > BMAX) B = BMAX;

    grad_kernel<<<dim3(WW / 32, HH / 8, B), dim3(32, 8)>>>(x);
    hog_kernel<<<dim3(OH * OW, B), 256>>>();
    domh_kernel<<<dim3(OH, B), 256>>>();
    vpass_kernel<<<dim3(32, 2, B), 256>>>((float*)d_out);
}

// round 11
// speedup vs baseline: 1.4674x; 1.4674x over previous
#include <cuda_runtime.h>

constexpr int HH = 512;
constexpr int WW = 512;
constexpr int NB = 9;
constexpr int OH = 32;
constexpr int OW = 32;
constexpr int BMAX = 8;

#define PIF 3.14159265358979323846f

// ---------------- scratch ----------------
__device__ float2 g_vab[BMAX * HH * WW];           // (wa*I, wb*I) per pixel
__device__ unsigned char g_k0[BMAX * HH * WW];     // base bin in [0,7]
__device__ float g_hog [BMAX * NB * OH * OW];
__device__ float g_maxn[BMAX];                     // atomicMax accumulator (>=0)
__device__ float g_tmp [BMAX * 2 * OH * WW];       // horizontally-resized rows
__device__ float g_wt  [WW * 6];
__device__ int   g_ws  [WW];

// ---------------- fused grayscale + gradient + bin decomposition (+ lanczos wt fold) ----------------
__global__ void grad_kernel(const float* __restrict__ x) {
    __shared__ float sg[10][34];
    int b = blockIdx.z;
    int x0 = blockIdx.x * 32, y0 = blockIdx.y * 8;
    const float* xb = x + (size_t)b * 3 * HH * WW;
    int tid = threadIdx.y * 32 + threadIdx.x;

    if (tid == 0) g_maxn[b] = 0.0f;   // reset for hog's atomicMax

    // fold: lanczos3 weight table, computed once by the first row of blocks of batch 0
    if (blockIdx.z == 0 && blockIdx.y == 0) {
        int o = blockIdx.x * 256 + tid;
        if (o < WW) {
            float sf = (o + 0.5f) * 0.0625f - 0.5f;
            int i0 = (int)floorf(sf) - 2;
            float w[6];
            float tot = 0.0f;
#pragma unroll
            for (int j = 0; j < 6; j++) {
                int ii = i0 + j;
                float val = 0.0f;
                if (ii >= 0 && ii < OW) {
                    float xx = fabsf(sf - (float)ii);
                    float px1 = PIF * xx;
                    float s1 = (xx == 0.0f) ? 1.0f : (sinf(px1) / px1);
                    float x3 = xx / 3.0f;
                    float px3 = PIF * x3;
                    float s3 = (x3 == 0.0f) ? 1.0f : (sinf(px3) / px3);
                    val = 3.0f * s1 * s3;
                }
                w[j] = val;
                tot += val;
            }
#pragma unroll
            for (int j = 0; j < 6; j++) g_wt[o * 6 + j] = w[j] / tot;
            g_ws[o] = i0;
        }
    }

    for (int i = tid; i < 10 * 34; i += 256) {
        int ly = i / 34, lx = i - ly * 34;
        int gy = y0 + ly - 1, gx = x0 + lx - 1;
        float v = 0.0f;
        if (gy >= 0 && gy < HH && gx >= 0 && gx < WW) {
            int p = gy * WW + gx;
            v = 0.299f * xb[p] + 0.587f * xb[p + HH * WW] + 0.114f * xb[p + 2 * HH * WW];
        }
        sg[ly][lx] = v;
    }
    __syncthreads();

    int lx = threadIdx.x, ly = threadIdx.y;
    float gx = sg[ly + 1][lx + 2] - sg[ly + 1][lx];
    float gy = sg[ly + 2][lx + 1] - sg[ly][lx + 1];
    float inten = sqrtf(gx * gx + gy * gy);
    float a = atan2f(gy, gx) + PIF;      // >= 0
    float r = fmodf(a, PIF);             // jnp.mod (positive arg) == fmod
    float o = r / PIF * 180.0f;          // [0,180)

    int k0 = (int)floorf((o - 10.0f) * 0.05f);   // [-1,8]
    float c0 = 10.0f + 20.0f * (float)k0;
    float wa = fminf(fmaxf(1.0f - (fabsf(o - c0) * 9.0f) / 180.0f, 0.0f), 1.0f);
    float wb = fminf(fmaxf(1.0f - (fabsf(o - (c0 + 20.0f)) * 9.0f) / 180.0f, 0.0f), 1.0f);
    float va = wa * inten, vb = wb * inten;
    if (k0 < 0)      { k0 = 0; va = vb; vb = 0.0f; }
    else if (k0 > 7) { k0 = 7; vb = va; va = 0.0f; }

    int p = b * HH * WW + (y0 + ly) * WW + (x0 + lx);
    g_vab[p] = make_float2(va, vb);
    g_k0[p] = (unsigned char)k0;
}

__device__ __forceinline__ int refl(int m) {
    m = (m < 0) ? -m : m;
    m = (m > HH - 1) ? (2 * (HH - 1) - m) : m;
    return m;
}

// ---------------- HOG aggregation + fused per-cell norm -> atomicMax ----------------
__global__ void hog_kernel() {
    __shared__ float sacc[NB][256];     // bank(tid) independent of bin -> conflict-free
    __shared__ int srow[33], scol[33];
    __shared__ float sbin[NB];
    int b = blockIdx.y;
    int cell = blockIdx.x;
    int oy = cell >> 5, ox = cell & 31;
    int tid = threadIdx.x;

    if (tid < 33) {
        srow[tid] = refl(oy * 16 - 16 + tid) * WW;
        scol[tid] = refl(ox * 16 - 16 + tid);
    }
#pragma unroll
    for (int k = 0; k < NB; k++) sacc[k][tid] = 0.0f;
    __syncthreads();

    const float2* __restrict__ V = g_vab + b * HH * WW;
    const unsigned char* __restrict__ K = g_k0 + b * HH * WW;

    // 1089 taps: 4 per thread + tail of 65
    float2 v[4]; float f[4]; int kk[4];
#pragma unroll
    for (int j = 0; j < 4; j++) {
        int t = tid + j * 256;
        int dy = t / 33;
        int dx = t - dy * 33;
        int gi = srow[dy] + scol[dx];
        v[j] = __ldg(&V[gi]);
        kk[j] = (int)K[gi];
        float fy = (float)(dy - 16), fx = (float)(dx - 16);
        f[j] = 1.0f - sqrtf(fy * fy + fx * fx) / 22.627417f;
    }
#pragma unroll
    for (int j = 0; j < 4; j++) {
        sacc[kk[j]][tid]     += f[j] * v[j].x;
        sacc[kk[j] + 1][tid] += f[j] * v[j].y;
    }
    if (tid < 65) {
        int t = 1024 + tid;
        int dy = t / 33;
        int dx = t - dy * 33;
        int gi = srow[dy] + scol[dx];
        float2 vt = __ldg(&V[gi]);
        int kt = (int)K[gi];
        float fy = (float)(dy - 16), fx = (float)(dx - 16);
        float ft = 1.0f - sqrtf(fy * fy + fx * fx) / 22.627417f;
        sacc[kt][tid]     += ft * vt.x;
        sacc[kt + 1][tid] += ft * vt.y;
    }
    __syncthreads();

    // warp w reduces bins k = w, w+8 (strided LDS + shuffle tree)
    int w = tid >> 5, l = tid & 31;
    for (int k = w; k < NB; k += 8) {
        float s = 0.0f;
#pragma unroll
        for (int i = 0; i < 8; i++) s += sacc[k][l + 32 * i];
#pragma unroll
        for (int off = 16; off > 0; off >>= 1)
            s += __shfl_down_sync(0xffffffffu, s, off);
        if (l == 0) {
            g_hog[(b * NB + k) * (OH * OW) + cell] = s;
            sbin[k] = s;
        }
    }
    __syncthreads();

    // cell L2 norm over bins -> per-batch max (atomic on int view; all values >= 0)
    if (tid == 0) {
        float s2 = 0.0f;
#pragma unroll
        for (int k = 0; k < NB; k++) s2 += sbin[k] * sbin[k];
        atomicMax((int*)&g_maxn[b], __float_as_int(sqrtf(s2)));
    }
}

// ---------------- fused dominant-direction + quantize + horizontal lanczos pass ----------------
// block = (row, b): dom for 32 cells of this row (threads 0-31), then hpass 2ch x 512.
__global__ void domh_kernel() {
    __shared__ float qs[2][OW];
    int b = blockIdx.y;
    int row = blockIdx.x;              // 0..31
    int tid = threadIdx.x;             // 256

    if (tid < OW) {
        int p = row * OW + tid;
        float maxn = g_maxn[b];
        float A = 0.0f, Cc = 0.0f, Bs = 0.0f;
#pragma unroll
        for (int k = 0; k < NB; k++) {
            float ck = 10.0f + 20.0f * (float)k;
            float th = (ck / 180.0f) * PIF;
            float sn = sinf(th), cs = cosf(th);
            float hn = g_hog[(b * NB + k) * (OH * OW) + p] / maxn;
            float h2 = hn * hn;
            A  += (sn * sn) * h2;
            Cc += (cs * cs) * h2;
            Bs += (sn * cs) * h2;
        }
        float Bb = -Bs;
        float half = (A - Cc) * 0.5f;
        float lam = (A + Cc) * 0.5f + sqrtf(half * half + Bb * Bb);
        float la = lam - A, lc = lam - Cc;
        float n1 = Bb * Bb + la * la;
        float n2 = lc * lc + Bb * Bb;
        bool use1 = (n1 >= n2);
        float vx = use1 ? Bb : lc;
        float vy = use1 ? la : Bb;
        float nrm = sqrtf(vx * vx + vy * vy) + 1e-9f;
        qs[0][tid] = floorf((vx / nrm + 1.0f) / 2.0f * 255.0f);
        qs[1][tid] = floorf((vy / nrm + 1.0f) / 2.0f * 255.0f);
    }
    __syncthreads();

    // horizontal pass: 2 channels x 512 outputs
    for (int i = tid; i < 2 * WW; i += 256) {
        int c = i >> 9;
        int xo = i & 511;
        int st = g_ws[xo];
        float s = 0.0f;
#pragma unroll
        for (int j = 0; j < 6; j++) {
            int idx = min(max(st + j, 0), OW - 1);
            s += g_wt[xo * 6 + j] * qs[c][idx];
        }
        g_tmp[(b * 2 + c) * (OH * WW) + row * WW + xo] = s;
    }
}

// ---------------- vertical pass + epilogue: one block per output row, float4 ----------------
__global__ void vpass_kernel(float* __restrict__ out) {
    int rowid = blockIdx.x;            // b * HH + y
    int b = rowid >> 9;
    int y = rowid & 511;
    int x4 = threadIdx.x * 4;          // 128 threads x 4 pixels

    // block-uniform: tap rows + weights
    int st = __ldg(&g_ws[y]);
    float w[6];
    int ro[6];
#pragma unroll
    for (int j = 0; j < 6; j++) {
        w[j] = __ldg(&g_wt[y * 6 + j]);
        ro[j] = min(max(st + j, 0), OH - 1) * WW;
    }

    const float* t0 = g_tmp + (b * 2 + 0) * (OH * WW);
    const float* t1 = g_tmp + (b * 2 + 1) * (OH * WW);

    float4 r0 = make_float4(0.f, 0.f, 0.f, 0.f);
    float4 r1 = make_float4(0.f, 0.f, 0.f, 0.f);
#pragma unroll
    for (int j = 0; j < 6; j++) {
        float4 a = __ldg((const float4*)(t0 + ro[j] + x4));
        float4 c = __ldg((const float4*)(t1 + ro[j] + x4));
        r0.x += w[j] * a.x; r0.y += w[j] * a.y; r0.z += w[j] * a.z; r0.w += w[j] * a.w;
        r1.x += w[j] * c.x; r1.y += w[j] * c.y; r1.z += w[j] * c.z; r1.w += w[j] * c.w;
    }

    float4 o0, o1;
    {
        float* pr0 = &r0.x; float* pr1 = &r1.x;
        float* po0 = &o0.x; float* po1 = &o1.x;
#pragma unroll
        for (int q = 0; q < 4; q++) {
            float a = fminf(fmaxf(rintf(pr0[q]), 0.0f), 255.0f);
            float c = fminf(fmaxf(rintf(pr1[q]), 0.0f), 255.0f);
            // (a/255 - 0.5)*2  ->  fmaf(a, 1/255, -0.5)*2   (<=1 ulp)
            float u = fmaf(a, 0.003921568859f, -0.5f) * 2.0f;
            float v = fmaf(c, 0.003921568859f, -0.5f) * 2.0f;
            // u/sqrt(u^2+v^2) -> u * rsqrt(u^2+v^2)  (~2 ulp, 1e-3 tol)
            float rn = __frsqrt_rn(fmaf(u, u, v * v));
            po0[q] = u * rn;
            po1[q] = v * rn;
        }
    }
    *(float4*)(out + ((size_t)(b * 2 + 0) * HH + y) * WW + x4) = o0;
    *(float4*)(out + ((size_t)(b * 2 + 1) * HH + y) * WW + x4) = o1;
}

// ---------------- launch ----------------
extern "C" void kernel_launch(void* const* d_in, const int* in_sizes, int n_in,
                              void* d_out, int out_size) {
    const float* x = (const float*)d_in[0];
    int B = in_sizes[0] / (3 * HH * WW);
    if (B > BMAX) B = BMAX;

    grad_kernel<<<dim3(WW / 32, HH / 8, B), dim3(32, 8)>>>(x);
    hog_kernel<<<dim3(OH * OW, B), 256>>>();
    domh_kernel<<<dim3(OH, B), 256>>>();
    vpass_kernel<<<B * HH, 128>>>((float*)d_out);
}

// round 12
// speedup vs baseline: 1.4886x; 1.0145x over previous
#include <cuda_runtime.h>

constexpr int HH = 512;
constexpr int WW = 512;
constexpr int NB = 9;
constexpr int OH = 32;
constexpr int OW = 32;
constexpr int BMAX = 8;

#define PIF 3.14159265358979323846f

// ---------------- scratch ----------------
__device__ float2 g_vab[BMAX * HH * WW];           // (wa*I, wb*I) per pixel
__device__ unsigned char g_k0[BMAX * HH * WW];     // base bin in [0,7]
__device__ float g_hog [BMAX * NB * OH * OW];
__device__ float g_maxn[BMAX];                     // atomicMax accumulator (>=0)
__device__ float g_tmp [BMAX * 2 * OH * WW];       // horizontally-resized rows
__device__ float g_wt  [WW * 6];
__device__ int   g_ws  [WW];

// ---------------- fused grayscale + gradient + bin decomposition (+ lanczos wt fold) ----------------
__global__ void grad_kernel(const float* __restrict__ x) {
    __shared__ float sg[10][34];
    int b = blockIdx.z;
    int x0 = blockIdx.x * 32, y0 = blockIdx.y * 8;
    const float* xb = x + (size_t)b * 3 * HH * WW;
    int tid = threadIdx.y * 32 + threadIdx.x;

    if (tid == 0) g_maxn[b] = 0.0f;   // reset for hog's atomicMax

    // fold: lanczos3 weight table, computed once by the first row of blocks of batch 0
    if (blockIdx.z == 0 && blockIdx.y == 0) {
        int o = blockIdx.x * 256 + tid;
        if (o < WW) {
            float sf = (o + 0.5f) * 0.0625f - 0.5f;
            int i0 = (int)floorf(sf) - 2;
            float w[6];
            float tot = 0.0f;
#pragma unroll
            for (int j = 0; j < 6; j++) {
                int ii = i0 + j;
                float val = 0.0f;
                if (ii >= 0 && ii < OW) {
                    float xx = fabsf(sf - (float)ii);
                    float px1 = PIF * xx;
                    float s1 = (xx == 0.0f) ? 1.0f : (sinf(px1) / px1);
                    float x3 = xx / 3.0f;
                    float px3 = PIF * x3;
                    float s3 = (x3 == 0.0f) ? 1.0f : (sinf(px3) / px3);
                    val = 3.0f * s1 * s3;
                }
                w[j] = val;
                tot += val;
            }
#pragma unroll
            for (int j = 0; j < 6; j++) g_wt[o * 6 + j] = w[j] / tot;
            g_ws[o] = i0;
        }
    }

    for (int i = tid; i < 10 * 34; i += 256) {
        int ly = i / 34, lx = i - ly * 34;
        int gy = y0 + ly - 1, gx = x0 + lx - 1;
        float v = 0.0f;
        if (gy >= 0 && gy < HH && gx >= 0 && gx < WW) {
            int p = gy * WW + gx;
            v = 0.299f * xb[p] + 0.587f * xb[p + HH * WW] + 0.114f * xb[p + 2 * HH * WW];
        }
        sg[ly][lx] = v;
    }
    __syncthreads();

    int lx = threadIdx.x, ly = threadIdx.y;
    float gx = sg[ly + 1][lx + 2] - sg[ly + 1][lx];
    float gy = sg[ly + 2][lx + 1] - sg[ly][lx + 1];
    float inten = sqrtf(gx * gx + gy * gy);
    float a = atan2f(gy, gx) + PIF;      // >= 0
    float r = fmodf(a, PIF);             // jnp.mod (positive arg) == fmod
    float o = r / PIF * 180.0f;          // [0,180)

    int k0 = (int)floorf((o - 10.0f) * 0.05f);   // [-1,8]
    float c0 = 10.0f + 20.0f * (float)k0;
    float wa = fminf(fmaxf(1.0f - (fabsf(o - c0) * 9.0f) / 180.0f, 0.0f), 1.0f);
    float wb = fminf(fmaxf(1.0f - (fabsf(o - (c0 + 20.0f)) * 9.0f) / 180.0f, 0.0f), 1.0f);
    float va = wa * inten, vb = wb * inten;
    if (k0 < 0)      { k0 = 0; va = vb; vb = 0.0f; }
    else if (k0 > 7) { k0 = 7; vb = va; va = 0.0f; }

    int p = b * HH * WW + (y0 + ly) * WW + (x0 + lx);
    g_vab[p] = make_float2(va, vb);
    g_k0[p] = (unsigned char)k0;
}

__device__ __forceinline__ int refl(int m) {
    m = (m < 0) ? -m : m;
    m = (m > HH - 1) ? (2 * (HH - 1) - m) : m;
    return m;
}

// ---------------- HOG aggregation + fused per-cell norm -> atomicMax ----------------
__global__ void hog_kernel() {
    __shared__ float sacc[NB][256];     // bank(tid) independent of bin -> conflict-free
    __shared__ int srow[33], scol[33];
    __shared__ float sbin[NB];
    int b = blockIdx.y;
    int cell = blockIdx.x;
    int oy = cell >> 5, ox = cell & 31;
    int tid = threadIdx.x;

    if (tid < 33) {
        srow[tid] = refl(oy * 16 - 16 + tid) * WW;
        scol[tid] = refl(ox * 16 - 16 + tid);
    }
#pragma unroll
    for (int k = 0; k < NB; k++) sacc[k][tid] = 0.0f;
    __syncthreads();

    const float2* __restrict__ V = g_vab + b * HH * WW;
    const unsigned char* __restrict__ K = g_k0 + b * HH * WW;

    // 1089 taps: 4 per thread + tail of 65
    float2 v[4]; float f[4]; int kk[4];
#pragma unroll
    for (int j = 0; j < 4; j++) {
        int t = tid + j * 256;
        int dy = t / 33;
        int dx = t - dy * 33;
        int gi = srow[dy] + scol[dx];
        v[j] = __ldg(&V[gi]);
        kk[j] = (int)K[gi];
        float fy = (float)(dy - 16), fx = (float)(dx - 16);
        f[j] = 1.0f - sqrtf(fy * fy + fx * fx) / 22.627417f;
    }
#pragma unroll
    for (int j = 0; j < 4; j++) {
        sacc[kk[j]][tid]     += f[j] * v[j].x;
        sacc[kk[j] + 1][tid] += f[j] * v[j].y;
    }
    if (tid < 65) {
        int t = 1024 + tid;
        int dy = t / 33;
        int dx = t - dy * 33;
        int gi = srow[dy] + scol[dx];
        float2 vt = __ldg(&V[gi]);
        int kt = (int)K[gi];
        float fy = (float)(dy - 16), fx = (float)(dx - 16);
        float ft = 1.0f - sqrtf(fy * fy + fx * fx) / 22.627417f;
        sacc[kt][tid]     += ft * vt.x;
        sacc[kt + 1][tid] += ft * vt.y;
    }
    __syncthreads();

    // warp w reduces bins k = w, w+8 (strided LDS + shuffle tree)
    int w = tid >> 5, l = tid & 31;
    for (int k = w; k < NB; k += 8) {
        float s = 0.0f;
#pragma unroll
        for (int i = 0; i < 8; i++) s += sacc[k][l + 32 * i];
#pragma unroll
        for (int off = 16; off > 0; off >>= 1)
            s += __shfl_down_sync(0xffffffffu, s, off);
        if (l == 0) {
            g_hog[(b * NB + k) * (OH * OW) + cell] = s;
            sbin[k] = s;
        }
    }
    __syncthreads();

    // cell L2 norm over bins -> per-batch max (atomic on int view; all values >= 0)
    if (tid == 0) {
        float s2 = 0.0f;
#pragma unroll
        for (int k = 0; k < NB; k++) s2 += sbin[k] * sbin[k];
        atomicMax((int*)&g_maxn[b], __float_as_int(sqrtf(s2)));
    }
}

// ---------------- fused dominant-direction + quantize + horizontal lanczos pass ----------------
// block = (row, b): dom for 32 cells of this row (threads 0-31), then hpass 2ch x 512.
__global__ void domh_kernel() {
    __shared__ float qs[2][OW];
    int b = blockIdx.y;
    int row = blockIdx.x;              // 0..31
    int tid = threadIdx.x;             // 256

    if (tid < OW) {
        int p = row * OW + tid;
        float maxn = g_maxn[b];
        float A = 0.0f, Cc = 0.0f, Bs = 0.0f;
#pragma unroll
        for (int k = 0; k < NB; k++) {
            float ck = 10.0f + 20.0f * (float)k;
            float th = (ck / 180.0f) * PIF;
            float sn = sinf(th), cs = cosf(th);
            float hn = g_hog[(b * NB + k) * (OH * OW) + p] / maxn;
            float h2 = hn * hn;
            A  += (sn * sn) * h2;
            Cc += (cs * cs) * h2;
            Bs += (sn * cs) * h2;
        }
        float Bb = -Bs;
        float half = (A - Cc) * 0.5f;
        float lam = (A + Cc) * 0.5f + sqrtf(half * half + Bb * Bb);
        float la = lam - A, lc = lam - Cc;
        float n1 = Bb * Bb + la * la;
        float n2 = lc * lc + Bb * Bb;
        bool use1 = (n1 >= n2);
        float vx = use1 ? Bb : lc;
        float vy = use1 ? la : Bb;
        float nrm = sqrtf(vx * vx + vy * vy) + 1e-9f;
        qs[0][tid] = floorf((vx / nrm + 1.0f) / 2.0f * 255.0f);
        qs[1][tid] = floorf((vy / nrm + 1.0f) / 2.0f * 255.0f);
    }
    __syncthreads();

    // horizontal pass: 2 channels x 512 outputs
    for (int i = tid; i < 2 * WW; i += 256) {
        int c = i >> 9;
        int xo = i & 511;
        int st = g_ws[xo];
        float s = 0.0f;
#pragma unroll
        for (int j = 0; j < 6; j++) {
            int idx = min(max(st + j, 0), OW - 1);
            s += g_wt[xo * 6 + j] * qs[c][idx];
        }
        g_tmp[(b * 2 + c) * (OH * WW) + row * WW + xo] = s;
    }
}

// ---------------- vertical pass + epilogue: 8 output rows per block, taps in registers ----------------
// st = g_ws[y] is constant across each aligned 8-row group, so the 6 tap rows
// (x 2 channels = 12 float4 loads) are loaded ONCE per thread and reused for 8 rows.
__global__ void vpass_kernel(float* __restrict__ out) {
    int gid = blockIdx.x;              // b * 64 + group
    int b = gid >> 6;
    int grp = gid & 63;
    int y0 = grp * 8;
    int x4 = threadIdx.x * 4;          // 128 threads x 4 pixels

    int st = __ldg(&g_ws[y0]);         // identical for all 8 rows in this group
    const float* t0 = g_tmp + (b * 2 + 0) * (OH * WW);
    const float* t1 = g_tmp + (b * 2 + 1) * (OH * WW);

    float4 ta[6], tc[6];
#pragma unroll
    for (int j = 0; j < 6; j++) {
        int ro = min(max(st + j, 0), OH - 1) * WW;
        ta[j] = __ldg((const float4*)(t0 + ro + x4));
        tc[j] = __ldg((const float4*)(t1 + ro + x4));
    }

    float* base0 = out + ((size_t)(b * 2 + 0) * HH + y0) * WW + x4;
    float* base1 = out + ((size_t)(b * 2 + 1) * HH + y0) * WW + x4;

#pragma unroll
    for (int ry = 0; ry < 8; ry++) {
        int y = y0 + ry;
        float4 r0 = make_float4(0.f, 0.f, 0.f, 0.f);
        float4 r1 = make_float4(0.f, 0.f, 0.f, 0.f);
#pragma unroll
        for (int j = 0; j < 6; j++) {
            float wj = __ldg(&g_wt[y * 6 + j]);
            r0.x += wj * ta[j].x; r0.y += wj * ta[j].y; r0.z += wj * ta[j].z; r0.w += wj * ta[j].w;
            r1.x += wj * tc[j].x; r1.y += wj * tc[j].y; r1.z += wj * tc[j].z; r1.w += wj * tc[j].w;
        }

        float4 o0, o1;
        float* pr0 = &r0.x; float* pr1 = &r1.x;
        float* po0 = &o0.x; float* po1 = &o1.x;
#pragma unroll
        for (int q = 0; q < 4; q++) {
            float a = fminf(fmaxf(rintf(pr0[q]), 0.0f), 255.0f);
            float c = fminf(fmaxf(rintf(pr1[q]), 0.0f), 255.0f);
            float u = fmaf(a, 0.003921568859f, -0.5f) * 2.0f;
            float v = fmaf(c, 0.003921568859f, -0.5f) * 2.0f;
            float rn = __frsqrt_rn(fmaf(u, u, v * v));
            po0[q] = u * rn;
            po1[q] = v * rn;
        }
        *(float4*)(base0 + ry * WW) = o0;
        *(float4*)(base1 + ry * WW) = o1;
    }
}

// ---------------- launch ----------------
extern "C" void kernel_launch(void* const* d_in, const int* in_sizes, int n_in,
                              void* d_out, int out_size) {
    const float* x = (const float*)d_in[0];
    int B = in_sizes[0] / (3 * HH * WW);
    if (B > BMAX) B = BMAX;

    grad_kernel<<<dim3(WW / 32, HH / 8, B), dim3(32, 8)>>>(x);
    hog_kernel<<<dim3(OH * OW, B), 256>>>();
    domh_kernel<<<dim3(OH, B), 256>>>();
    vpass_kernel<<<B * 64, 128>>>((float*)d_out);
}